// round 9
// baseline (speedup 1.0000x reference)
#include <cuda_runtime.h>
#include <math.h>
#include <stdint.h>

#define Bq 2
#define Lq 5
#define Cq 64
#define Hq 128
#define Wq 256
#define HWq 32768
#define NHWq 327680
#define OUTQ 4194304

#define NBLK 128           // persistent blocks (<=148 SMs, 1 per SM)
#define NTHR 512           // 16 warps; warp w owns channels [4w,4w+4)
#define PXB  512           // pixels per block (2 rows)
#define CHK  32            // pixels per pipeline chunk
#define NCHK (PXB / CHK)   // 16
#define NBUF 3
#define TILEF (Lq * Cq * CHK)   // 10240 floats = 40 KB per buffer

// ---------------- scratch (all slots fully overwritten per launch; replay-safe) ----------------
__device__ float        g_sum_r[64][Bq * Cq];
__device__ float        g_max_r[64][Bq * Cq];
__device__ int          g_cnt_blk[NBLK];
__device__ unsigned int g_arrive;               // monotonic across graph replays

// 5x5 Gaussian, sigma=1: 1/(2*pi*sigma) * exp(-(dx^2+dy^2)/2)  (NOT normalized, matches ref)
__constant__ float GK[25] = {
    0.0029150243f, 0.0130642333f, 0.0215392793f, 0.0130642333f, 0.0029150243f,
    0.0130642333f, 0.0585498315f, 0.0965323526f, 0.0585498315f, 0.0130642333f,
    0.0215392793f, 0.0965323526f, 0.1591549431f, 0.0965323526f, 0.0215392793f,
    0.0130642333f, 0.0585498315f, 0.0965323526f, 0.0585498315f, 0.0130642333f,
    0.0029150243f, 0.0130642333f, 0.0215392793f, 0.0130642333f, 0.0029150243f
};

__device__ __forceinline__ float fsig(float x) { return 1.0f / (1.0f + __expf(-x)); }

// ---- smem layout (floats) ----
#define TCW 260
#define TCH 6
#define NF_BUF   (NBUF * TILEF)            // 30720
#define NF_SC    (Lq * TCH * TCW)          // 7800
#define NF_MASK  (Lq * PXB)                // 2560
#define NF_PART  (16 * Lq * 32)            // 2560
#define SMEM_FLOATS (NF_BUF + NF_SC + NF_MASK + NF_PART + 160 + 64 + 64 + 5 + 5 + 128 + 128 + 64 + 129 + 8)
#define SMEM_TOTAL (SMEM_FLOATS * 4)

__global__ void __launch_bounds__(NTHR, 1) hpha_persistent(
        const float* __restrict__ x,
        const float* __restrict__ psm,
        const float* __restrict__ inv_delay,
        const float* __restrict__ ew_w,
        const float* __restrict__ ew_b,
        const float* __restrict__ ewc_w,
        const float* __restrict__ ewc_b,
        const float* __restrict__ w1,
        const float* __restrict__ w2,
        float* __restrict__ out, int out_size) {
    extern __shared__ float sm[];
    float* buf    = sm;                         // [3][5*64*32]
    float* sc     = buf + NF_BUF;               // [5][6][260]
    float* s_mask = sc + NF_SC;                 // [5][512]
    float* s_part = s_mask + NF_MASK;           // [16][5][32]
    float* s_dot  = s_part + NF_PART;           // [5][32]
    float* s_psum = s_dot + 160;                // [64]
    float* s_pmax = s_psum + 64;                // [64]
    float* s_enc  = s_pmax + 64;                // [5]
    float* s_enw  = s_enc + 5;                  // [5]
    float* s_avg  = s_enw + 5;                  // [128]
    float* s_mx   = s_avg + 128;                // [128]
    float* s_gate = s_mx + 128;                 // [64]
    int*   s_red  = (int*)(s_gate + 64);        // [128]
    int*   s_cnt  = s_red + 128;                // [1]

    const int tid  = threadIdx.x;
    const int blk  = blockIdx.x;
    const int b    = blk >> 6;                  // batch
    const int s    = blk & 63;                  // pixel-range id = private pool slot
    const int P0   = s * PXB;
    const int r0   = s * 2;
    const int lane = tid & 31;
    const int wid  = tid >> 5;
    const int cbase = wid * 4;

    // ---- cp.async chunk issue: 2560 x 16B per chunk, 5 per thread ----
    auto issue_chunk = [&](int ck) {
        float* dst = buf + (ck % NBUF) * TILEF;
        const float* src0 = x + (size_t)(b * Lq * Cq) * HWq + P0 + ck * CHK;
#pragma unroll
        for (int k = 0; k < 5; k++) {
            int j = tid + k * NTHR;             // 0..2559 = (l*64+c)*8 + q
            int q  = j & 7;
            int lc = j >> 3;                    // l*64+c
            const float* gp = src0 + (size_t)lc * HWq + q * 4;
            uint32_t sa = (uint32_t)__cvta_generic_to_shared(dst + lc * CHK + q * 4);
            asm volatile("cp.async.cg.shared.global [%0], [%1], 16;" :: "r"(sa), "l"(gp));
        }
        asm volatile("cp.async.commit_group;");
    };

    // prologue: kick 3 chunks of x DMA before mask work (overlap)
    issue_chunk(0); issue_chunk(1); issue_chunk(2);

    // ---------------- phase 0: local mask (smem only) ----------------
    if (tid < 2 * Lq) {
        int l = tid % Lq;
        float v = tanhf(inv_delay[b * Lq + l] * ((tid < Lq) ? ewc_w[0] : ew_w[0])
                        + ((tid < Lq) ? ewc_b[0] : ew_b[0])) + 1.0f;
        if (tid < Lq) s_enc[l] = v; else s_enw[l] = v;
    }
    if (tid == 0) *s_cnt = 0;
    __syncthreads();

    for (int idx = tid; idx < Lq * TCH * TCW; idx += NTHR) {
        int l  = idx / (TCH * TCW);
        int r2 = idx - l * (TCH * TCW);
        int tr = r2 / TCW;
        int tc = r2 - tr * TCW;
        int h = r0 - 2 + tr, w = tc - 2;
        float v = 0.0f;
        if (h >= 0 && h < Hq && w >= 0 && w < Wq) {
            int n = b * Lq + l;
            int gi = h * Wq + w;
            float a = psm[(size_t)(n * 2 + 0) * HWq + gi];
            float c = psm[(size_t)(n * 2 + 1) * HWq + gi];
            v = fmaxf(fsig(a), fsig(c)) * s_enc[l];
        }
        sc[idx] = v;
    }
    __syncthreads();

    for (int idx = tid; idx < Lq * PXB; idx += NTHR) {
        int l   = idx >> 9;
        int px  = idx & 511;
        int tr  = (px >> 8) + 2;
        int col = px & 255;
        const float* t = sc + l * (TCH * TCW);
        float acc = 0.0f;
#pragma unroll
        for (int dy = 0; dy < 5; dy++)
#pragma unroll
            for (int dx = 0; dx < 5; dx++)
                acc += GK[dy * 5 + dx] * t[(tr + dy - 2) * TCW + col + dx];
        float m = (acc > 0.01f || l == 0) ? 1.0f : 0.0f;
        s_mask[idx] = m;
        unsigned bal = __ballot_sync(0xffffffffu, m > 0.5f);
        if (lane == 0) atomicAdd(s_cnt, __popc(bal));
    }
    __syncthreads();
    if (tid == 0) g_cnt_blk[blk] = *s_cnt;

    // ---------------- phase 1: pipelined fuse from smem tiles ----------------
    float psum[4] = {0.f, 0.f, 0.f, 0.f};
    float pmax[4] = {-INFINITY, -INFINITY, -INFINITY, -INFINITY};

    for (int it = 0; it < NCHK; it++) {
        asm volatile("cp.async.wait_group 2;");
        __syncthreads();
        const float* t = buf + (it % NBUF) * TILEF;
        int pxg = it * CHK + lane;

        // partial dots over this warp's 4 channels (lane = px -> conflict-free LDS)
        float x0[4];
#pragma unroll
        for (int c4 = 0; c4 < 4; c4++) x0[c4] = t[(cbase + c4) * CHK + lane];
        float pd[Lq];
        pd[0] = x0[0]*x0[0] + x0[1]*x0[1] + x0[2]*x0[2] + x0[3]*x0[3];
#pragma unroll
        for (int l = 1; l < Lq; l++) {
            float a = 0.0f;
#pragma unroll
            for (int c4 = 0; c4 < 4; c4++)
                a += x0[c4] * t[(l * Cq + cbase + c4) * CHK + lane];
            pd[l] = a;
        }
#pragma unroll
        for (int l = 0; l < Lq; l++) s_part[(wid * Lq + l) * 32 + lane] = pd[l];
        __syncthreads();

        if (tid < Lq * 32) {
            int l = tid >> 5, p2 = tid & 31;
            float a = 0.0f;
#pragma unroll
            for (int w = 0; w < 16; w++) a += s_part[(w * Lq + l) * 32 + p2];
            s_dot[l * 32 + p2] = a;
        }
        __syncthreads();

        // softmax coefs (per warp, lane = px)
        float sl[Lq], scv[Lq], mxv = -INFINITY;
#pragma unroll
        for (int l = 0; l < Lq; l++) sl[l] = s_enw[l] * s_mask[l * PXB + pxg];
#pragma unroll
        for (int l = 0; l < Lq; l++) {
            scv[l] = s_dot[l * 32 + lane] * sl[0] * sl[l] * 0.125f;   // 1/sqrt(64)
            mxv = fmaxf(mxv, scv[l]);
        }
        float es = 0.0f;
#pragma unroll
        for (int l = 0; l < Lq; l++) { scv[l] = __expf(scv[l] - mxv); es += scv[l]; }
        float inv = 1.0f / es;
        float coef[Lq];
#pragma unroll
        for (int l = 0; l < Lq; l++) coef[l] = scv[l] * inv * sl[l];

        // fused output (ungated) -> gmem (lands in L2), pools in registers
#pragma unroll
        for (int c4 = 0; c4 < 4; c4++) {
            float f = coef[0] * x0[c4];
#pragma unroll
            for (int l = 1; l < Lq; l++)
                f += coef[l] * t[(l * Cq + cbase + c4) * CHK + lane];
            out[(size_t)(b * Cq + cbase + c4) * HWq + P0 + pxg] = f;
            psum[c4] += f;
            pmax[c4] = fmaxf(pmax[c4], f);
        }
        __syncthreads();                       // buffer free before reissue
        if (it + NBUF < NCHK) issue_chunk(it + NBUF);
    }

    // pools: warp-reduce over pixels -> private global slot (plain stores, no atomics)
#pragma unroll
    for (int c4 = 0; c4 < 4; c4++) {
#pragma unroll
        for (int o = 16; o > 0; o >>= 1) {
            psum[c4] += __shfl_xor_sync(0xffffffffu, psum[c4], o);
            pmax[c4] = fmaxf(pmax[c4], __shfl_xor_sync(0xffffffffu, pmax[c4], o));
        }
    }
    if (lane == 0) {
#pragma unroll
        for (int c4 = 0; c4 < 4; c4++) {
            s_psum[cbase + c4] = psum[c4];
            s_pmax[cbase + c4] = pmax[c4];
        }
    }
    __syncthreads();
    if (tid < Cq) {
        g_sum_r[s][b * Cq + tid] = s_psum[tid];
        g_max_r[s][b * Cq + tid] = s_pmax[tid];
    }

    // ---------------- grid barrier (replay-safe, monotonic) ----------------
    if (tid == 0) {
        __threadfence();
        unsigned v = atomicAdd(&g_arrive, 1u);
        unsigned target = (v & ~127u) + 128u;
        unsigned cur;
        do {
            asm volatile("ld.acquire.gpu.u32 %0, [%1];" : "=r"(cur) : "l"(&g_arrive));
        } while (cur < target);
    }
    __syncthreads();

    // ---------------- phase 2: gate MLP + comm_rate + scale (out re-read hits L2) ----------------
    if (tid < Bq * Cq) {
        float a = 0.0f, m = -INFINITY;
#pragma unroll 8
        for (int k = 0; k < 64; k++) {
            a += __ldcg(&g_sum_r[k][tid]);
            m = fmaxf(m, __ldcg(&g_max_r[k][tid]));
        }
        s_avg[tid] = a * (1.0f / HWq);
        s_mx[tid]  = m;
    } else if (tid < Bq * Cq + NBLK) {
        s_red[tid - Bq * Cq] = __ldcg(&g_cnt_blk[tid - Bq * Cq]);
    }
    __syncthreads();

    if (tid < Cq) {
        float og = 0.0f;
#pragma unroll
        for (int j = 0; j < 4; j++) {
            float sa = 0.0f, smv = 0.0f;
            for (int cc = 0; cc < Cq; cc++) {
                float w = w1[j * Cq + cc];
                sa  += s_avg[b * Cq + cc] * w;
                smv += s_mx[b * Cq + cc] * w;
            }
            og += (fmaxf(sa, 0.0f) + fmaxf(smv, 0.0f)) * w2[tid * 4 + j];
        }
        s_gate[tid] = 1.0f / (1.0f + expf(-og));
    }
    __syncthreads();

    if (blk == 0 && tid == 0) {
        int t = 0;
#pragma unroll 8
        for (int k = 0; k < NBLK; k++) t += s_red[k];
        if (out_size > OUTQ) out[OUTQ] = (float)t / (float)NHWq;
    }

    float4* ob4 = (float4*)(out + (size_t)b * Cq * HWq + P0);
#pragma unroll 4
    for (int k = 0; k < 16; k++) {
        int idx = k * NTHR + tid;              // 8192 float4 per block
        int c = idx >> 7, off = idx & 127;
        float4 v = __ldcg(&ob4[(size_t)c * (HWq / 4) + off]);
        float g = s_gate[c];
        v.x *= g; v.y *= g; v.z *= g; v.w *= g;
        ob4[(size_t)c * (HWq / 4) + off] = v;
    }
}

// ---------------- launch ----------------
extern "C" void kernel_launch(void* const* d_in, const int* in_sizes, int n_in,
                              void* d_out, int out_size) {
    const float* x         = (const float*)d_in[0];
    const float* psm       = (const float*)d_in[1];
    const float* inv_delay = (const float*)d_in[2];
    const float* ew_w      = (const float*)d_in[3];
    const float* ew_b      = (const float*)d_in[4];
    const float* ewc_w     = (const float*)d_in[5];
    const float* ewc_b     = (const float*)d_in[6];
    const float* sta_w1    = (const float*)d_in[7];
    const float* sta_w2    = (const float*)d_in[8];
    float* out = (float*)d_out;

    cudaFuncSetAttribute(hpha_persistent,
                         cudaFuncAttributeMaxDynamicSharedMemorySize, SMEM_TOTAL);
    hpha_persistent<<<NBLK, NTHR, SMEM_TOTAL>>>(
        x, psm, inv_delay, ew_w, ew_b, ewc_w, ewc_b, sta_w1, sta_w2, out, out_size);
}

// round 10
// speedup vs baseline: 1.0962x; 1.0962x over previous
#include <cuda_runtime.h>
#include <math.h>

#define Bq 2
#define Lq 5
#define Nq 10
#define Cq 64
#define Hq 128
#define Wq 256
#define HWq (Hq * Wq)          // 32768
#define NHWq (Nq * HWq)        // 327680
#define OUTQ (Bq * Cq * HWq)   // 4194304

#define MGX (Wq / 64)          // 4
#define MGY (Hq / 4)           // 32
#define MASK_BLOCKS (MGX * MGY * Nq)   // 1280

#define NSLOT 64               // pooling replication factor (decontends L2 atomics)

// ---------------- scratch (no allocations allowed) ----------------
__device__ float        g_mask[NHWq];
__device__ float        g_sum_r[NSLOT][Bq * Cq];
__device__ unsigned int g_max_r[NSLOT][Bq * Cq];   // monotonic-encoded float max
__device__ float        g_gate[Bq * Cq];
__device__ int          g_blkcnt[MASK_BLOCKS];

// separable 5-tap Gaussian, sigma=1:  k2d = (1/2pi) * g1[dy] * g1[dx],  g1 = exp(-d^2/2)
__constant__ float GX[5] = {0.13533528f, 0.60653066f, 1.0f, 0.60653066f, 0.13533528f};
__constant__ float GY[5] = {0.13533528f * 0.15915494f, 0.60653066f * 0.15915494f,
                            0.15915494f, 0.60653066f * 0.15915494f, 0.13533528f * 0.15915494f};

__device__ __forceinline__ float fsig(float x) { return 1.0f / (1.0f + __expf(-x)); }

// monotonic float<->uint order-preserving encode (max identity = 0u)
__device__ __forceinline__ unsigned int fenc(float f) {
    unsigned int u = __float_as_uint(f);
    return (u & 0x80000000u) ? ~u : (u | 0x80000000u);
}
__device__ __forceinline__ float fdec(unsigned int e) {
    return __uint_as_float((e & 0x80000000u) ? (e & 0x7FFFFFFFu) : ~e);
}

// ============ kernel 1: conf + SEPARABLE gaussian + mask (smem halo, 2-stage) ============
__global__ void __launch_bounds__(256) conf_mask_kernel(
        const float* __restrict__ psm,
        const float* __restrict__ inv_delay,
        const float* __restrict__ ewc_w,
        const float* __restrict__ ewc_b) {
    const int TX = 64, TY = 4;
    __shared__ float sc[TY + 4][TX + 4];   // conf with 2-halo (8 x 68)
    __shared__ float ht[TY + 4][TX];       // horizontal-filtered (8 x 64)
    __shared__ int s_cnt;

    int n  = blockIdx.z;
    int w0 = blockIdx.x * TX;
    int h0 = blockIdx.y * TY;
    int tid = threadIdx.x;
    int flat = (n * MGY + blockIdx.y) * MGX + blockIdx.x;

    // re-init replicated pooling scratch each replay (first NSLOT blocks; stream-ordered)
    if (flat < NSLOT) {
        if (tid < Bq * Cq)            g_sum_r[flat][tid] = 0.0f;
        else if (tid < 2 * Bq * Cq)   g_max_r[flat][tid - Bq * Cq] = 0u;
    }
    if (tid == 0) s_cnt = 0;

    float enc = tanhf(inv_delay[n] * ewc_w[0] + ewc_b[0]) + 1.0f;
    const float* p0 = psm + (size_t)(n * 2 + 0) * HWq;
    const float* p1 = psm + (size_t)(n * 2 + 1) * HWq;

    // stage 1: conf tile with halo (544 elements, 256 threads)
#pragma unroll
    for (int k = 0; k < 3; k++) {
        int i = tid + k * 256;
        if (i < (TY + 4) * (TX + 4)) {
            int sy = i / (TX + 4);
            int sx = i - sy * (TX + 4);
            int h = h0 + sy - 2, w = w0 + sx - 2;
            float v = 0.0f;                               // zero-pad = 'SAME'
            if (h >= 0 && h < Hq && w >= 0 && w < Wq) {
                int idx = h * Wq + w;
                v = fmaxf(fsig(p0[idx]), fsig(p1[idx])) * enc;
            }
            sc[sy][sx] = v;
        }
    }
    __syncthreads();

    // stage 2: horizontal 5-tap (512 elements, 2 per thread)
#pragma unroll
    for (int k = 0; k < 2; k++) {
        int i = tid + k * 256;          // i = sy*64 + sx
        int sy = i >> 6, sx = i & 63;
        float a = 0.0f;
#pragma unroll
        for (int d = 0; d < 5; d++) a += GX[d] * sc[sy][sx + d];
        ht[sy][sx] = a;
    }
    __syncthreads();

    // stage 3: vertical 5-tap + threshold + ego + count
    int tx = tid & 63, ty = tid >> 6;
    float acc = 0.0f;
#pragma unroll
    for (int d = 0; d < 5; d++) acc += GY[d] * ht[ty + d][tx];

    float m = (acc > 0.01f) ? 1.0f : 0.0f;
    if (n % Lq == 0) m = 1.0f;                            // ego always communicates
    g_mask[(size_t)n * HWq + (h0 + ty) * Wq + (w0 + tx)] = m;

    unsigned bal = __ballot_sync(0xffffffffu, m > 0.5f);
    if ((tid & 31) == 0) atomicAdd(&s_cnt, __popc(bal));
    __syncthreads();
    if (tid == 0) g_blkcnt[flat] = s_cnt;
}

// ============ kernel 2: single-pass attention + pooling (8 warps, 8 ch/warp) ============
// R6-proven shape; __launch_bounds__(256,4) caps regs at 64 so 4 CTAs co-reside per SM,
// letting one CTA's load burst overlap another's compute/atomic tail.
__global__ void __launch_bounds__(256, 4) fuse_kernel(
        const float* __restrict__ x,
        const float* __restrict__ inv_delay,
        const float* __restrict__ ew_w,
        const float* __restrict__ ew_b,
        float* __restrict__ out) {
    __shared__ float s_part[8][Lq][32];
    __shared__ float s_enw[Lq];

    int b    = blockIdx.y;
    int lane = threadIdx.x & 31;
    int wid  = threadIdx.x >> 5;
    int p    = blockIdx.x * 32 + lane;
    int slot = blockIdx.x & (NSLOT - 1);

    if (threadIdx.x < Lq)
        s_enw[threadIdx.x] = tanhf(inv_delay[b * Lq + threadIdx.x] * ew_w[0] + ew_b[0]) + 1.0f;

    // x loads issued first (front-batched for MLP); mask loads follow
    const float* xb = x + ((size_t)(b * Lq) * Cq + wid * 8) * HWq + p;
    float xv[8][Lq];
#pragma unroll
    for (int c = 0; c < 8; c++)
#pragma unroll
        for (int l = 0; l < Lq; l++)
            xv[c][l] = xb[((size_t)l * Cq + c) * HWq];

    float mk[Lq];
#pragma unroll
    for (int l = 0; l < Lq; l++) mk[l] = g_mask[(size_t)(b * Lq + l) * HWq + p];

    float pd[Lq] = {0.f, 0.f, 0.f, 0.f, 0.f};
#pragma unroll
    for (int c = 0; c < 8; c++) {
        float e = xv[c][0];
#pragma unroll
        for (int l = 0; l < Lq; l++) pd[l] += e * xv[c][l];
    }
#pragma unroll
    for (int l = 0; l < Lq; l++) s_part[wid][l][lane] = pd[l];
    __syncthreads();

    float dot[Lq];
#pragma unroll
    for (int l = 0; l < Lq; l++) {
        float t = 0.0f;
#pragma unroll
        for (int w = 0; w < 8; w++) t += s_part[w][l][lane];
        dot[l] = t;
    }

    float s[Lq];
#pragma unroll
    for (int l = 0; l < Lq; l++) s[l] = s_enw[l] * mk[l];

    float scv[Lq], mx = -INFINITY;
#pragma unroll
    for (int l = 0; l < Lq; l++) {
        scv[l] = dot[l] * s[0] * s[l] * 0.125f;           // 1/sqrt(64)
        mx = fmaxf(mx, scv[l]);
    }
    float esum = 0.0f;
#pragma unroll
    for (int l = 0; l < Lq; l++) { scv[l] = __expf(scv[l] - mx); esum += scv[l]; }
    float inv = 1.0f / esum;
    float coef[Lq];
#pragma unroll
    for (int l = 0; l < Lq; l++) coef[l] = scv[l] * inv * s[l];

    float* ob = out + ((size_t)b * Cq + wid * 8) * HWq + p;
    int cbase = b * Cq + wid * 8;
#pragma unroll
    for (int c = 0; c < 8; c++) {
        float f = 0.0f;
#pragma unroll
        for (int l = 0; l < Lq; l++) f += coef[l] * xv[c][l];
        ob[(size_t)c * HWq] = f;
        float ws = f, wm = f;
#pragma unroll
        for (int o = 16; o > 0; o >>= 1) {
            ws += __shfl_xor_sync(0xffffffffu, ws, o);
            wm = fmaxf(wm, __shfl_xor_sync(0xffffffffu, wm, o));
        }
        if (lane == 0) {
            atomicAdd(&g_sum_r[slot][cbase + c], ws);         // decontended RED.ADD
            atomicMax(&g_max_r[slot][cbase + c], fenc(wm));   // decontended RED.MAX.U32
        }
    }
}

// ============ kernel 3: fold slots + gate MLP + comm_rate (single small block) ============
__global__ void __launch_bounds__(256) reduce_gate_kernel(
        const float* __restrict__ w1,   // (4,64)
        const float* __restrict__ w2,   // (64,4)
        float* __restrict__ out, int out_size) {
    __shared__ float s_avg[Bq * Cq];
    __shared__ float s_mx[Bq * Cq];
    __shared__ int s_red[256];

    int tid = threadIdx.x;

    if (tid < Bq * Cq) {
        float a = 0.0f;
#pragma unroll 8
        for (int s = 0; s < NSLOT; s++) a += g_sum_r[s][tid];
        s_avg[tid] = a * (1.0f / HWq);
    } else {
        int c = tid - Bq * Cq;
        unsigned int e = 0u;
#pragma unroll 8
        for (int s = 0; s < NSLOT; s++) e = max(e, g_max_r[s][c]);
        s_mx[c] = fdec(e);
    }

    int t = 0;
    for (int i = tid; i < MASK_BLOCKS; i += 256) t += g_blkcnt[i];
    s_red[tid] = t;
    __syncthreads();

    if (tid < Bq * Cq) {
        int b = tid >> 6, c = tid & 63;
        float og = 0.0f;
#pragma unroll
        for (int j = 0; j < 4; j++) {
            float sa = 0.0f, sm = 0.0f;
            for (int cc = 0; cc < Cq; cc++) {
                float w = w1[j * Cq + cc];
                sa += s_avg[b * Cq + cc] * w;
                sm += s_mx[b * Cq + cc] * w;
            }
            og += (fmaxf(sa, 0.0f) + fmaxf(sm, 0.0f)) * w2[c * 4 + j];
        }
        g_gate[tid] = 1.0f / (1.0f + expf(-og));
    }

    for (int st = 128; st > 0; st >>= 1) {
        __syncthreads();
        if (tid < st) s_red[tid] += s_red[tid + st];
    }
    if (tid == 0 && out_size > OUTQ)
        out[OUTQ] = (float)s_red[0] / (float)NHWq;
}

// ============ kernel 4: pure streaming gate apply (R6 version) ============
__global__ void __launch_bounds__(256) scale_kernel(float* __restrict__ out) {
    int cg = blockIdx.x >> 5;             // 1024 floats per block; 32 blocks per channel
    float g = g_gate[cg];
    float4* o4 = (float4*)out + (size_t)blockIdx.x * 256 + threadIdx.x;
    float4 v = *o4;
    v.x *= g; v.y *= g; v.z *= g; v.w *= g;
    *o4 = v;
}

// ---------------- launch ----------------
extern "C" void kernel_launch(void* const* d_in, const int* in_sizes, int n_in,
                              void* d_out, int out_size) {
    const float* x         = (const float*)d_in[0];
    const float* psm       = (const float*)d_in[1];
    const float* inv_delay = (const float*)d_in[2];
    const float* ew_w      = (const float*)d_in[3];
    const float* ew_b      = (const float*)d_in[4];
    const float* ewc_w     = (const float*)d_in[5];
    const float* ewc_b     = (const float*)d_in[6];
    const float* sta_w1    = (const float*)d_in[7];
    const float* sta_w2    = (const float*)d_in[8];
    float* out = (float*)d_out;

    dim3 gm(MGX, MGY, Nq);
    conf_mask_kernel<<<gm, 256>>>(psm, inv_delay, ewc_w, ewc_b);
    dim3 gf(HWq / 32, Bq);
    fuse_kernel<<<gf, 256>>>(x, inv_delay, ew_w, ew_b, out);
    reduce_gate_kernel<<<1, 256>>>(sta_w1, sta_w2, out, out_size);
    scale_kernel<<<OUTQ / 1024, 256>>>(out);
}